// round 5
// baseline (speedup 1.0000x reference)
#include <cuda_runtime.h>

// SpixelNet_geom: mean over (B,N) of per-area masked variance, single kernel.
// m = dr(dr(mask)); Sm=Σm, Sa=Σg·m, Sb=Σg·m³, Sc=Σg²·m⁴, Sd=Σm²
// varr = (Sc - 2·mean·Sb + mean²·Sd)/msum, mean = Sa/msum, msum = Sm+EPS.

#define TWO_PI_F     6.28318530717958647692f
#define INV_TWO_PI_F 0.15915494309189533577f
#define EPS_F        1e-8f

__device__ float    g_acc    = 0.0f;
__device__ unsigned g_ticket = 0u;

// Block = 256 threads = 8 warps. Each warp owns 8 consecutive areas.
// A warp iteration j covers 2 areas (one per 16-lane segment): each LDG.128
// spans 512 B contiguous (perfect coalescing, 4 lines). All 8 loads are
// front-batched -> MLP=8; the 4 reduction chains are independent and overlap.
__global__ __launch_bounds__(256, 4)
void area_loss_kernel(const float4* __restrict__ img4,
                      const float4* __restrict__ msk4,
                      float* __restrict__ out,
                      float scale, unsigned nBlocks) {
    const int tid  = threadIdx.x;
    const int warp = tid >> 5;
    const int lane = tid & 31;
    const int seg  = lane >> 4;   // 0/1: area within the j-pair
    const int l16  = lane & 15;   // lane within 16-lane segment

    // float4 index of this thread's j=0 element
    const int base4 = (((blockIdx.x << 6) + (warp << 3) + seg) << 4) + l16;

    // front-batch ALL loads (each warp-LDG = 512 B contiguous)
    const float4 iv0 = img4[base4      ];
    const float4 iv1 = img4[base4 + 32 ];
    const float4 iv2 = img4[base4 + 64 ];
    const float4 iv3 = img4[base4 + 96 ];
    const float4 mv0 = msk4[base4      ];
    const float4 mv1 = msk4[base4 + 32 ];
    const float4 mv2 = msk4[base4 + 64 ];
    const float4 mv3 = msk4[base4 + 96 ];

    const float4 ivs[4] = {iv0, iv1, iv2, iv3};
    const float4 mvs[4] = {mv0, mv1, mv2, mv3};

    float acc = 0.0f;

    #pragma unroll
    for (int j = 0; j < 4; ++j) {
        const float gs[4] = {ivs[j].x, ivs[j].y, ivs[j].z, ivs[j].w};
        const float xs[4] = {mvs[j].x, mvs[j].y, mvs[j].z, mvs[j].w};

        float Sm = 0.f, Sa = 0.f, Sb = 0.f, Sc = 0.f, Sd = 0.f;

        #pragma unroll
        for (int e = 0; e < 4; ++e) {
            float x  = xs[e];
            float s1 = __sinf(TWO_PI_F * x);
            float y  = fmaf(-INV_TWO_PI_F, s1, x);   // diff_round(x)
            float s2 = __sinf(TWO_PI_F * y);
            float m  = fmaf(-INV_TWO_PI_F, s2, y);   // diff_round(diff_round(x))

            float g  = gs[e];
            float im = g * m;        // g*m
            float m2 = m * m;        // m^2
            float u  = im * m;       // g*m^2

            Sm += m;
            Sa += im;
            Sb = fmaf(im, m2, Sb);   // g*m^3
            Sc = fmaf(u,  u,  Sc);   // g^2*m^4
            Sd = fmaf(m,  m,  Sd);   // m^2
        }

        // width-16 segmented reduction (stays inside the segment)
        #pragma unroll
        for (int off = 8; off >= 1; off >>= 1) {
            Sm += __shfl_xor_sync(0xffffffffu, Sm, off);
            Sa += __shfl_xor_sync(0xffffffffu, Sa, off);
            Sb += __shfl_xor_sync(0xffffffffu, Sb, off);
            Sc += __shfl_xor_sync(0xffffffffu, Sc, off);
            Sd += __shfl_xor_sync(0xffffffffu, Sd, off);
        }

        if (l16 == 0) {
            float msum = Sm + EPS_F;
            float mean = Sa / msum;
            float num  = fmaf(mean * mean, Sd, fmaf(-2.0f * mean, Sb, Sc));
            acc += num / msum;       // varr for this area
        }
    }

    // combine the two segment leaders of the warp
    acc += __shfl_xor_sync(0xffffffffu, acc, 16);

    __shared__ float smem[8];
    if (lane == 0) smem[warp] = acc;
    __syncthreads();

    if (tid < 8) {
        float w = smem[tid];
        w += __shfl_xor_sync(0x000000ffu, w, 4);
        w += __shfl_xor_sync(0x000000ffu, w, 2);
        w += __shfl_xor_sync(0x000000ffu, w, 1);
        if (tid == 0) {
            atomicAdd(&g_acc, w);
            __threadfence();
            unsigned t = atomicAdd(&g_ticket, 1u);
            if (t == nBlocks - 1u) {           // last block finalizes
                *out     = g_acc * scale;
                g_acc    = 0.0f;               // reset for next graph replay
                g_ticket = 0u;
                __threadfence();
            }
        }
    }
}

extern "C" void kernel_launch(void* const* d_in, const int* in_sizes, int n_in,
                              void* d_out, int out_size) {
    const float* img = (const float*)d_in[0];   // sv_area_image [8,16384,8,8]
    const float* msk = (const float*)d_in[1];   // sv_area_mask  [8,16384,8,8]
    float* out = (float*)d_out;

    const int total  = in_sizes[0];      // 8*16384*64 = 8388608
    const int nAreas = total / 64;       // 131072
    const float scale = 1.0f / (float)nAreas;

    const unsigned blocks = (unsigned)(nAreas / 64);   // 2048
    area_loss_kernel<<<blocks, 256>>>((const float4*)img,
                                      (const float4*)msk,
                                      out, scale, blocks);
}

// round 9
// speedup vs baseline: 1.1382x; 1.1382x over previous
#include <cuda_runtime.h>

// SpixelNet_geom: mean over (B,N) of per-area masked variance, single kernel.
// m = dr(dr(mask)); per area: msum=Σm+EPS, mean=Σ(g·m)/msum,
// dev = g·m² − mean·m ;  varr = Σ dev² / msum.  out = mean(varr).

#define TWO_PI_F     6.28318530717958647692f
#define INV_TWO_PI_F 0.15915494309189533577f
#define EPS_F        1e-8f

typedef unsigned long long ull;

__device__ __forceinline__ ull pk(float lo, float hi) {
    ull r; asm("mov.b64 %0, {%1, %2};" : "=l"(r) : "f"(lo), "f"(hi)); return r;
}
__device__ __forceinline__ void upk(float& lo, float& hi, ull v) {
    asm("mov.b64 {%0, %1}, %2;" : "=f"(lo), "=f"(hi) : "l"(v));
}
__device__ __forceinline__ ull mul2(ull a, ull b) {
    ull d; asm("mul.rn.f32x2 %0, %1, %2;" : "=l"(d) : "l"(a), "l"(b)); return d;
}
__device__ __forceinline__ ull add2(ull a, ull b) {
    ull d; asm("add.rn.f32x2 %0, %1, %2;" : "=l"(d) : "l"(a), "l"(b)); return d;
}
__device__ __forceinline__ ull fma2(ull a, ull b, ull c) {
    ull d; asm("fma.rn.f32x2 %0, %1, %2, %3;" : "=l"(d) : "l"(a), "l"(b), "l"(c)); return d;
}

// packed diff_round: x - sin(2*pi*x)/(2*pi), elementwise on f32x2
__device__ __forceinline__ ull dr2(ull x) {
    const ull TWOPI2  = pk(TWO_PI_F, TWO_PI_F);
    const ull NINV2PI = pk(-INV_TWO_PI_F, -INV_TWO_PI_F);
    ull t = mul2(x, TWOPI2);
    float tl, th; upk(tl, th, t);
    ull s = pk(__sinf(tl), __sinf(th));
    return fma2(NINV2PI, s, x);
}

__device__ float    g_acc    = 0.0f;
__device__ unsigned g_ticket = 0u;

// Block = 256 threads = 8 warps; warp owns 8 consecutive areas, processed as
// 4 iterations of 2 areas (one per 16-lane segment). Each warp LDG.128 spans
// 512 B contiguous (perfect coalescing).
__global__ __launch_bounds__(256, 6)
void area_loss_kernel(const float4* __restrict__ img4,
                      const float4* __restrict__ msk4,
                      float* __restrict__ out,
                      float scale, unsigned nBlocks) {
    const int tid  = threadIdx.x;
    const int warp = tid >> 5;
    const int lane = tid & 31;
    const int seg  = lane >> 4;   // 0/1: area within the pair
    const int l16  = lane & 15;

    const int base4 = (((blockIdx.x << 6) + (warp << 3) + seg) << 4) + l16;

    float acc = 0.0f;

    #pragma unroll
    for (int j = 0; j < 4; ++j) {
        const float4 iv = img4[base4 + j * 32];
        const float4 mv = msk4[base4 + j * 32];

        ull g01 = pk(iv.x, iv.y), g23 = pk(iv.z, iv.w);
        ull x01 = pk(mv.x, mv.y), x23 = pk(mv.z, mv.w);

        ull m01 = dr2(dr2(x01));
        ull m23 = dr2(dr2(x23));

        ull im01 = mul2(g01, m01), im23 = mul2(g23, m23);   // g*m
        ull u01  = mul2(im01, m01), u23 = mul2(im23, m23);  // g*m^2

        // local Sm, Sa (collapse packed -> scalar)
        ull sm2 = add2(m01, m23);
        ull sa2 = add2(im01, im23);
        float a, b;
        upk(a, b, sm2); float Sm = a + b;
        upk(a, b, sa2); float Sa = a + b;

        // width-16 butterfly: every lane ends with segment totals
        #pragma unroll
        for (int off = 8; off >= 1; off >>= 1) {
            Sm += __shfl_xor_sync(0xffffffffu, Sm, off);
            Sa += __shfl_xor_sync(0xffffffffu, Sa, off);
        }

        const float msum = Sm + EPS_F;
        const float mean = __fdividef(Sa, msum);
        const ull  nmean2 = pk(-mean, -mean);

        // dev = g*m^2 - mean*m ; r = sum(dev^2), local then reduced
        ull d01 = fma2(nmean2, m01, u01);
        ull d23 = fma2(nmean2, m23, u23);
        ull r2  = fma2(d01, d01, mul2(d23, d23));
        upk(a, b, r2); float r = a + b;

        #pragma unroll
        for (int off = 8; off >= 1; off >>= 1)
            r += __shfl_xor_sync(0xffffffffu, r, off);

        if (l16 == 0) acc += __fdividef(r, msum);   // varr for this area
    }

    // combine the two segment leaders of the warp
    acc += __shfl_xor_sync(0xffffffffu, acc, 16);

    __shared__ float smem[8];
    if (lane == 0) smem[warp] = acc;
    __syncthreads();

    if (tid < 8) {
        float w = smem[tid];
        w += __shfl_xor_sync(0x000000ffu, w, 4);
        w += __shfl_xor_sync(0x000000ffu, w, 2);
        w += __shfl_xor_sync(0x000000ffu, w, 1);
        if (tid == 0) {
            atomicAdd(&g_acc, w);
            __threadfence();
            unsigned t = atomicAdd(&g_ticket, 1u);
            if (t == nBlocks - 1u) {           // last block finalizes
                *out     = g_acc * scale;
                g_acc    = 0.0f;               // reset for next graph replay
                g_ticket = 0u;
                __threadfence();
            }
        }
    }
}

extern "C" void kernel_launch(void* const* d_in, const int* in_sizes, int n_in,
                              void* d_out, int out_size) {
    const float* img = (const float*)d_in[0];   // sv_area_image [8,16384,8,8]
    const float* msk = (const float*)d_in[1];   // sv_area_mask  [8,16384,8,8]
    float* out = (float*)d_out;

    const int total  = in_sizes[0];      // 8*16384*64 = 8388608
    const int nAreas = total / 64;       // 131072
    const float scale = 1.0f / (float)nAreas;

    const unsigned blocks = (unsigned)(nAreas / 64);   // 2048
    area_loss_kernel<<<blocks, 256>>>((const float4*)img,
                                      (const float4*)msk,
                                      out, scale, blocks);
}